// round 10
// baseline (speedup 1.0000x reference)
#include <cuda_runtime.h>

// Problem constants
#define NPT   4096      // B*H*W = 4*32*32 output points
#define NOC   64        // output channels
#define NFEAT 576       // IC*K*K unfolded features
#define NGRP  144       // 4-feature groups
#define NCH   5         // subarray chunks (29,29,29,29,28 groups)
#define PM    2048      // points handled by the MMA role (multiple of 16)
#define MMA_BLOCKS ((PM / 16) * (NOC / 16))         // 512
#define DP_OBLK 4
#define DP_PTS  (NPT - PM)                          // 2048
#define DP_PB   (DP_PTS / 128)                      // 16
#define DP_BLOCKS (DP_PB * (NOC / DP_OBLK) * NCH)   // 16*16*5 = 1280

// Scratch (no allocations allowed -> device globals)
__device__ float    g_maxabs;
__device__ unsigned g_wpos[NOC * NFEAT];        // [o][t][g] packed bytes (dp4a B)
__device__ unsigned g_wneg[NOC * NFEAT];
__device__ unsigned g_wpk[NCH * 8 * NOC * 32];  // [ch][tpn][oc][kw] (mma B), pads 0
__device__ uint4    g_sv2[NGRP * NPT];          // [g][pt] stream words s0..s3
__device__ int      g_part[NCH * NOC * NPT];    // per-chunk partials (dp4a half)
__device__ int      g_spart[4 * NOC * NPT];     // per-stream partials (mma half)

// ---------------------------------------------------------------- max |w|
__global__ void k_maxabs(const float* __restrict__ w, int n) {
    __shared__ float red[32];
    float m = 0.f;
    for (int i = threadIdx.x; i < n; i += blockDim.x)
        m = fmaxf(m, fabsf(w[i]));
    for (int o = 16; o; o >>= 1) m = fmaxf(m, __shfl_xor_sync(0xffffffffu, m, o));
    if ((threadIdx.x & 31) == 0) red[threadIdx.x >> 5] = m;
    __syncthreads();
    if (threadIdx.x < 32) {
        int nw = (blockDim.x + 31) >> 5;
        m = (threadIdx.x < nw) ? red[threadIdx.x] : 0.f;
        for (int o = 16; o; o >>= 1) m = fmaxf(m, __shfl_xor_sync(0xffffffffu, m, o));
        if (threadIdx.x == 0) g_maxabs = (m > 0.f) ? m : 1.f;
    }
}

// ---------------- weight bit-slicing: both dp4a and mma layouts
__global__ void k_weights(const float* __restrict__ w) {
    int idx = blockIdx.x * blockDim.x + threadIdx.x;   // NOC * NCH * 32
    if (idx >= NOC * NCH * 32) return;
    int kw = idx & 31;
    int ch = (idx >> 5) % NCH;
    int o  = idx / (NCH * 32);
    int ng = (ch == 4) ? 28 : 29;
    unsigned pw[4] = {0,0,0,0}, nw[4] = {0,0,0,0};
    if (kw < ng) {
        float ma = g_maxabs;
        int g = ch * 29 + kw;
#pragma unroll
        for (int j = 0; j < 4; j++) {
            float r  = w[o * NFEAT + 4 * g + j];
            float wp = fmaxf(r, 0.f);
            float wn = fmaxf(-r, 0.f);
            int pi = (int)rintf(__fdiv_rn(wp, ma) * 255.f);
            int ni = (int)rintf(__fdiv_rn(wn, ma) * 255.f);
#pragma unroll
            for (int t = 0; t < 4; t++) {
                pw[t] |= (unsigned)((pi >> (2 * t)) & 3) << (8 * j);
                nw[t] |= (unsigned)((ni >> (2 * t)) & 3) << (8 * j);
            }
        }
    }
#pragma unroll
    for (int t = 0; t < 4; t++) {
        g_wpk[((ch * 8 + t) * NOC + o) * 32 + kw]     = pw[t];
        g_wpk[((ch * 8 + 4 + t) * NOC + o) * 32 + kw] = nw[t];
    }
    if (kw < ng) {
        int g = ch * 29 + kw;
#pragma unroll
        for (int t = 0; t < 4; t++) {
            g_wpos[o * NFEAT + t * NGRP + g] = pw[t];
            g_wneg[o * NFEAT + t * NGRP + g] = nw[t];
        }
    }
}

// -------------- input quantize + unfold + bit-stream pack ([g][pt] uint4)
__global__ void k_streams(const float* __restrict__ x) {
    int id = blockIdx.x * blockDim.x + threadIdx.x;   // NPT*NGRP
    if (id >= NPT * NGRP) return;
    int pt = id & (NPT - 1);
    int g  = id >> 12;
    int b = pt >> 10, p = pt & 1023, h = p >> 5, wc = p & 31;
    unsigned sw0 = 0, sw1 = 0, sw2 = 0, sw3 = 0;
#pragma unroll
    for (int j = 0; j < 4; j++) {
        int f = 4 * g + j;
        int c = f / 9, rem = f - 9 * c, kh = rem / 3, kw = rem - 3 * (rem / 3);
        int y = h + kh - 1, xx = wc + kw - 1;
        float v = 0.f;
        if ((unsigned)y < 32u && (unsigned)xx < 32u)
            v = x[((b * 64 + c) * 32 + y) * 32 + xx];
        v = fminf(fmaxf(v, -8.f), 7.9375f);
        int q = ((int)rintf(v * 16.f)) & 255;
        sw0 |= (unsigned)( q        & 3) << (8 * j);
        sw1 |= (unsigned)((q >> 2)  & 3) << (8 * j);
        sw2 |= (unsigned)((q >> 4)  & 3) << (8 * j);
        sw3 |= (unsigned)((q >> 6)  & 3) << (8 * j);
    }
    g_sv2[g * NPT + pt] = make_uint4(sw0, sw1, sw2, sw3);
}

// ---------------------------------------------------------------- mma op
__device__ __forceinline__ void mma_s8(int d[4], unsigned a0, unsigned a1,
                                       unsigned a2, unsigned a3,
                                       unsigned b0, unsigned b1) {
    asm volatile(
        "mma.sync.aligned.m16n8k32.row.col.s32.s8.s8.s32 "
        "{%0,%1,%2,%3}, {%4,%5,%6,%7}, {%8,%9}, {%0,%1,%2,%3};"
        : "+r"(d[0]), "+r"(d[1]), "+r"(d[2]), "+r"(d[3])
        : "r"(a0), "r"(a1), "r"(a2), "r"(a3), "r"(b0), "r"(b1));
}

// =========================== hybrid main kernel ===========================
// 128 threads, 24KB smem -> ~7 CTAs/SM for BOTH roles.
// Blocks [0, MMA_BLOCKS): IMMA role, pts [0, PM), tile 16 pt x 16 oc;
//   warp w = stream s; 2 oc-tiles; diffs kept in regs across chunks;
//   per-stream partials to g_spart.
// Blocks [MMA_BLOCKS, +DP_BLOCKS): dp4a role, pts [PM, NPT).
__global__ __launch_bounds__(128, 7) void k_hybrid() {
    __shared__ union {
        struct {
            unsigned a[4][4][32][4];     // [s][kb][lane][e]           8 KB
            unsigned b[8][4][2][2][32];  // [tpn][kb][ot][bsel][lane] 16 KB
        } m;
        struct { unsigned w[DP_OBLK][29][8]; } d;
    } sm;
    const int tid = threadIdx.x;

    if (blockIdx.x < MMA_BLOCKS) {
        // ---------------- MMA role: tile 16 pts x 16 oc ----------------
        const int warp = tid >> 5, lane = tid & 31;   // warp = stream s
        const int gid  = lane >> 2, tig = lane & 3;
        const int ptbase = (blockIdx.x >> 2) << 4;
        const int ocbase = (blockIdx.x & 3) << 4;

        int diffd[2][4];
#pragma unroll
        for (int ot = 0; ot < 2; ot++)
#pragma unroll
            for (int e = 0; e < 4; e++) diffd[ot][e] = 0;

        for (int c = 0; c < NCH; c++) {
            const int ng = (c == 4) ? 28 : 29;
            __syncthreads();
            // stage A in fragment order (16 pts x 32 kwords)
            for (int i = tid; i < 16 * 32; i += 128) {
                int pt = i >> 5, kw = i & 31;
                uint4 v = make_uint4(0, 0, 0, 0);
                if (kw < ng) v = g_sv2[(c * 29 + kw) * NPT + ptbase + pt];
                int ln = (pt & 7) * 4 + (kw & 3);
                int kb = kw >> 3;
                int e  = ((pt >> 3) & 1) | (((kw >> 2) & 1) << 1);
                sm.m.a[0][kb][ln][e] = v.x; sm.m.a[1][kb][ln][e] = v.y;
                sm.m.a[2][kb][ln][e] = v.z; sm.m.a[3][kb][ln][e] = v.w;
            }
            // stage B in fragment order (8 tpn x 16 oc x 32 kw)
            for (int i = tid; i < 8 * 16 * 8; i += 128) {
                int tpn = i >> 7, rest = i & 127;
                int oc16 = rest >> 3, kw4 = (rest & 7) * 4;
                uint4 v = *(const uint4*)&g_wpk[((c * 8 + tpn) * NOC + ocbase + oc16) * 32 + kw4];
                int ot = oc16 >> 3, g8 = (oc16 & 7) * 4;
                int kb = kw4 >> 3, bsel = (kw4 >> 2) & 1;
                unsigned* dst = &sm.m.b[tpn][kb][ot][bsel][g8];
                dst[0] = v.x; dst[1] = v.y; dst[2] = v.z; dst[3] = v.w;
            }
            __syncthreads();

#pragma unroll
            for (int ot = 0; ot < 2; ot++) {
                int acc[8][4];   // [t*2+pn][e]
#pragma unroll
                for (int i = 0; i < 8; i++)
#pragma unroll
                    for (int e = 0; e < 4; e++) acc[i][e] = 0;

#pragma unroll
                for (int kb = 0; kb < 4; kb++) {
                    uint4 av = *(const uint4*)&sm.m.a[warp][kb][lane][0];
#pragma unroll
                    for (int t = 0; t < 4; t++) {
                        unsigned p0 = sm.m.b[t][kb][ot][0][lane];
                        unsigned p1 = sm.m.b[t][kb][ot][1][lane];
                        mma_s8(acc[t * 2 + 0], av.x, av.y, av.z, av.w, p0, p1);
                        unsigned n0 = sm.m.b[4 + t][kb][ot][0][lane];
                        unsigned n1 = sm.m.b[4 + t][kb][ot][1][lane];
                        mma_s8(acc[t * 2 + 1], av.x, av.y, av.z, av.w, n0, n1);
                    }
                }
#pragma unroll
                for (int t = 0; t < 4; t++) {
                    int sh = 2 * (warp + t);
#pragma unroll
                    for (int e = 0; e < 4; e++)
                        diffd[ot][e] += (min(acc[t * 2][e], 31) - min(acc[t * 2 + 1][e], 31)) << sh;
                }
            }
        }

        // per-stream partial: g_spart[s][oc][pt]
#pragma unroll
        for (int ot = 0; ot < 2; ot++)
#pragma unroll
            for (int e = 0; e < 4; e++) {
                int pt = ptbase + gid + ((e & 2) ? 8 : 0);
                int oc = ocbase + ot * 8 + tig * 2 + (e & 1);
                g_spart[((warp * NOC + oc) << 12) + pt] = diffd[ot][e];
            }
    } else {
        // ---------------- dp4a role: 128 pts x 4 oc x 1 chunk ----------------
        const int bid   = blockIdx.x - MMA_BLOCKS;
        const int c     = bid / (DP_PB * 16);
        const int rest  = bid % (DP_PB * 16);
        const int obase = (rest % 16) * DP_OBLK;
        const int ptb   = PM + (rest / 16) * 128;
        const int g0    = c * 29;
        const int ng    = (c == 4) ? 28 : 29;
        const int pt    = ptb + tid;

        for (int i = tid; i < DP_OBLK * 29 * 8; i += 128) {
            int r = i & 7, rr = i >> 3;
            int gl = rr % 29, ol = rr / 29;
            unsigned v = 0;
            if (gl < ng) {
                const unsigned* src = (r < 4) ? g_wpos : g_wneg;
                v = src[(obase + ol) * NFEAT + (r & 3) * NGRP + g0 + gl];
            }
            sm.d.w[ol][gl][r] = v;
        }
        __syncthreads();

        const uint4* __restrict__ sv = g_sv2 + g0 * NPT + pt;

#pragma unroll 1
        for (int ol = 0; ol < DP_OBLK; ol++) {
            int accp[16], accn[16];
#pragma unroll
            for (int i = 0; i < 16; i++) { accp[i] = 0; accn[i] = 0; }
#pragma unroll 2
            for (int gl = 0; gl < ng; gl++) {
                uint4 a  = sv[gl * NPT];
                uint4 wp = *reinterpret_cast<const uint4*>(&sm.d.w[ol][gl][0]);
                uint4 wn = *reinterpret_cast<const uint4*>(&sm.d.w[ol][gl][4]);
                const unsigned av[4] = {a.x, a.y, a.z, a.w};
                const unsigned pv[4] = {wp.x, wp.y, wp.z, wp.w};
                const unsigned nv[4] = {wn.x, wn.y, wn.z, wn.w};
#pragma unroll
                for (int s = 0; s < 4; s++)
#pragma unroll
                    for (int t = 0; t < 4; t++) {
                        accp[s * 4 + t] = __dp4a((int)av[s], (int)pv[t], accp[s * 4 + t]);
                        accn[s * 4 + t] = __dp4a((int)av[s], (int)nv[t], accn[s * 4 + t]);
                    }
            }
            int diff = 0;
#pragma unroll
            for (int s = 0; s < 4; s++)
#pragma unroll
                for (int t = 0; t < 4; t++)
                    diff += (min(accp[s * 4 + t], 31) - min(accn[s * 4 + t], 31))
                            << (2 * (s + t));
            g_part[((c * NOC + obase + ol) << 12) + pt] = diff;
        }
    }
}

// -------------------- combine partials + scale (both halves)
__global__ void k_final(float* __restrict__ out) {
    int id = blockIdx.x * blockDim.x + threadIdx.x;   // NOC * NPT
    if (id >= NOC * NPT) return;
    int oc = id >> 12, pt = id & (NPT - 1);
    int b = pt >> 10, p = pt & 1023;
    int d = 0;
    if (pt < PM) {
#pragma unroll
        for (int s = 0; s < 4; s++)
            d += g_spart[((s * NOC + oc) << 12) + pt];
    } else {
#pragma unroll
        for (int c = 0; c < NCH; c++)
            d += g_part[((c * NOC + oc) << 12) + pt];
    }
    out[((b * NOC + oc) << 10) + p] = (float)d * (g_maxabs * (1.0f / 255.0f));
}

// zero any tail elements of d_out beyond the conv output
__global__ void k_tail(float* __restrict__ out, int start, int total) {
    int i = start + blockIdx.x * blockDim.x + threadIdx.x;
    if (i < total) out[i] = 0.f;
}

extern "C" void kernel_launch(void* const* d_in, const int* in_sizes, int n_in,
                              void* d_out, int out_size) {
    const float* x = (const float*)d_in[0];   // inputs (4,64,32,32)
    const float* w = (const float*)d_in[1];   // weight (64,64,3,3)
    float* out = (float*)d_out;

    k_maxabs <<<1, 1024>>>(w, in_sizes[1]);
    k_weights<<<(NOC * NCH * 32 + 255) / 256, 256>>>(w);
    k_streams<<<(NPT * NGRP + 255) / 256, 256>>>(x);
    k_hybrid <<<MMA_BLOCKS + DP_BLOCKS, 128>>>();
    k_final  <<<(NOC * NPT + 255) / 256, 256>>>(out);

    if (out_size > NPT * NOC) {
        int extra = out_size - NPT * NOC;
        k_tail<<<(extra + 255) / 256, 256>>>(out, NPT * NOC, out_size);
    }
}

// round 11
// speedup vs baseline: 1.6142x; 1.6142x over previous
#include <cuda_runtime.h>

// Problem constants
#define NPT   4096      // B*H*W = 4*32*32 output points
#define NOC   64        // output channels
#define NFEAT 576       // IC*K*K unfolded features
#define NGRP  144       // 4-feature groups
#define NCH   5         // subarray chunks (29,29,29,29,28 groups)
#define OBLK  4         // output channels per block in main kernel
#define PTB   128       // points per block (threads)

// Scratch (no allocations allowed -> device globals)
__device__ float    g_maxabs;
__device__ unsigned g_wpos[NOC * NFEAT];        // [o][t][g]
__device__ unsigned g_wneg[NOC * NFEAT];
__device__ uint4    g_sv2[NGRP * NPT];          // [g][pt] -> 4 stream words
__device__ int      g_part[NCH * NOC * NPT];    // per-chunk partial diffs

// ---------------------------------------------------------------- max |w|
__global__ void k_maxabs(const float* __restrict__ w, int n) {
    __shared__ float red[32];
    float m = 0.f;
    for (int i = threadIdx.x; i < n; i += blockDim.x)
        m = fmaxf(m, fabsf(w[i]));
    for (int o = 16; o; o >>= 1) m = fmaxf(m, __shfl_xor_sync(0xffffffffu, m, o));
    if ((threadIdx.x & 31) == 0) red[threadIdx.x >> 5] = m;
    __syncthreads();
    if (threadIdx.x < 32) {
        int nw = (blockDim.x + 31) >> 5;
        m = (threadIdx.x < nw) ? red[threadIdx.x] : 0.f;
        for (int o = 16; o; o >>= 1) m = fmaxf(m, __shfl_xor_sync(0xffffffffu, m, o));
        if (threadIdx.x == 0) g_maxabs = (m > 0.f) ? m : 1.f;
    }
}

// ---------------- fused prep: weight bit-slicing + input bit-streaming
// blocks [0, WB): weights; blocks [WB, WB+SB): streams
#define WB ((NOC * NGRP + 255) / 256)              // 36
#define SB ((NPT * NGRP + 255) / 256)              // 2304
__global__ void k_prep(const float* __restrict__ w, const float* __restrict__ x) {
    if (blockIdx.x < WB) {
        int idx = blockIdx.x * 256 + threadIdx.x;
        if (idx >= NOC * NGRP) return;
        int o = idx / NGRP, g = idx % NGRP;
        float ma = g_maxabs;
        unsigned pw[4] = {0,0,0,0}, nw[4] = {0,0,0,0};
#pragma unroll
        for (int j = 0; j < 4; j++) {
            float r  = w[o * NFEAT + 4 * g + j];
            float wp = fmaxf(r, 0.f);
            float wn = fmaxf(-r, 0.f);
            int pi = (int)rintf(__fdiv_rn(wp, ma) * 255.f);
            int ni = (int)rintf(__fdiv_rn(wn, ma) * 255.f);
#pragma unroll
            for (int t = 0; t < 4; t++) {
                pw[t] |= (unsigned)((pi >> (2 * t)) & 3) << (8 * j);
                nw[t] |= (unsigned)((ni >> (2 * t)) & 3) << (8 * j);
            }
        }
#pragma unroll
        for (int t = 0; t < 4; t++) {
            g_wpos[o * NFEAT + t * NGRP + g] = pw[t];
            g_wneg[o * NFEAT + t * NGRP + g] = nw[t];
        }
    } else {
        int id = (blockIdx.x - WB) * 256 + threadIdx.x;   // NPT*NGRP
        if (id >= NPT * NGRP) return;
        int pt = id & (NPT - 1);
        int g  = id >> 12;
        int b = pt >> 10, p = pt & 1023, h = p >> 5, wc = p & 31;
        unsigned sw0 = 0, sw1 = 0, sw2 = 0, sw3 = 0;
#pragma unroll
        for (int j = 0; j < 4; j++) {
            int f = 4 * g + j;
            int c = f / 9, rem = f - 9 * c, kh = rem / 3, kw = rem - 3 * (rem / 3);
            int y = h + kh - 1, xx = wc + kw - 1;
            float v = 0.f;
            if ((unsigned)y < 32u && (unsigned)xx < 32u)
                v = x[((b * 64 + c) * 32 + y) * 32 + xx];
            v = fminf(fmaxf(v, -8.f), 7.9375f);
            int q = ((int)rintf(v * 16.f)) & 255;
            sw0 |= (unsigned)( q        & 3) << (8 * j);
            sw1 |= (unsigned)((q >> 2)  & 3) << (8 * j);
            sw2 |= (unsigned)((q >> 4)  & 3) << (8 * j);
            sw3 |= (unsigned)((q >> 6)  & 3) << (8 * j);
        }
        g_sv2[g * NPT + pt] = make_uint4(sw0, sw1, sw2, sw3);
    }
}

// ---------------------------------------------------------- main dp4a MAC
// grid: (NPT/PTB, NOC/OBLK, NCH). Block: 128 points x OBLK oc x 1 chunk.
// (R3-proven configuration: best measured k_main = 79.4 us)
__global__ __launch_bounds__(PTB) void k_main() {
    __shared__ unsigned s_w[OBLK][29][8];    // [ol][gl][pos t0..3 | neg t0..3]
    const int tid   = threadIdx.x;
    const int pt    = blockIdx.x * PTB + tid;
    const int obase = blockIdx.y * OBLK;
    const int c     = blockIdx.z;
    const int g0    = c * 29;
    const int ng    = (c == 4) ? 28 : 29;

    for (int i = tid; i < OBLK * 29 * 8; i += PTB) {
        int r = i & 7, rest = i >> 3;
        int gl = rest % 29, ol = rest / 29;
        unsigned v = 0;
        if (gl < ng) {
            const unsigned* src = (r < 4) ? g_wpos : g_wneg;
            v = src[(obase + ol) * NFEAT + (r & 3) * NGRP + g0 + gl];
        }
        s_w[ol][gl][r] = v;
    }
    __syncthreads();

    const uint4* __restrict__ sv = g_sv2 + g0 * NPT + pt;

#pragma unroll 1
    for (int ol = 0; ol < OBLK; ol++) {
        int accp[16], accn[16];
#pragma unroll
        for (int i = 0; i < 16; i++) { accp[i] = 0; accn[i] = 0; }
#pragma unroll 2
        for (int gl = 0; gl < ng; gl++) {
            uint4 a  = sv[gl * NPT];                                      // LDG.128
            uint4 wp = *reinterpret_cast<const uint4*>(&s_w[ol][gl][0]);  // LDS.128
            uint4 wn = *reinterpret_cast<const uint4*>(&s_w[ol][gl][4]);  // LDS.128
            const unsigned av[4] = {a.x, a.y, a.z, a.w};
            const unsigned pv[4] = {wp.x, wp.y, wp.z, wp.w};
            const unsigned nv[4] = {wn.x, wn.y, wn.z, wn.w};
#pragma unroll
            for (int s = 0; s < 4; s++)
#pragma unroll
                for (int t = 0; t < 4; t++) {
                    accp[s * 4 + t] = __dp4a((int)av[s], (int)pv[t], accp[s * 4 + t]);
                    accn[s * 4 + t] = __dp4a((int)av[s], (int)nv[t], accn[s * 4 + t]);
                }
        }
        int diff = 0;
#pragma unroll
        for (int s = 0; s < 4; s++)
#pragma unroll
            for (int t = 0; t < 4; t++)
                diff += (min(accp[s * 4 + t], 31) - min(accn[s * 4 + t], 31))
                        << (2 * (s + t));
        g_part[((c * NOC + obase + ol) << 12) + pt] = diff;
    }
}

// -------------------- combine partials + scale + tail zero (fused)
__global__ void k_final(float* __restrict__ out, int out_size) {
    int id = blockIdx.x * blockDim.x + threadIdx.x;
    if (id < NOC * NPT) {
        int oc = id >> 12, pt = id & (NPT - 1);
        int b = pt >> 10, p = pt & 1023;
        int d = 0;
#pragma unroll
        for (int c = 0; c < NCH; c++)
            d += g_part[((c * NOC + oc) << 12) + pt];
        out[((b * NOC + oc) << 10) + p] = (float)d * (g_maxabs * (1.0f / 255.0f));
    } else if (id < out_size) {
        out[id] = 0.f;   // aux-loss scalar / padding tail
    }
}

extern "C" void kernel_launch(void* const* d_in, const int* in_sizes, int n_in,
                              void* d_out, int out_size) {
    const float* x = (const float*)d_in[0];   // inputs (4,64,32,32)
    const float* w = (const float*)d_in[1];   // weight (64,64,3,3)
    float* out = (float*)d_out;

    k_maxabs<<<1, 1024>>>(w, in_sizes[1]);
    k_prep  <<<WB + SB, 256>>>(w, x);
    k_main  <<<dim3(NPT / PTB, NOC / OBLK, NCH), PTB>>>();
    int fin = (out_size > NOC * NPT) ? out_size : NOC * NPT;
    k_final <<<(fin + 255) / 256, 256>>>(out, out_size);
}

// round 12
// speedup vs baseline: 1.7446x; 1.0808x over previous
#include <cuda_runtime.h>

// Problem constants
#define NPT   4096      // B*H*W = 4*32*32 output points
#define NOC   64        // output channels
#define NFEAT 576       // IC*K*K unfolded features
#define NGRP  144       // 4-feature groups
#define NGRP_PAD 160    // padded so prefetch beyond last chunk stays in bounds
#define NCH   5         // subarray chunks (29,29,29,29,28 groups)
#define OBLK  2         // output channels per block in main kernel
#define PTB   128       // points per block (threads)

// Scratch (no allocations allowed -> device globals)
__device__ float    g_maxabs;
__device__ unsigned g_wpos[NOC * NFEAT];        // [o][t][g]
__device__ unsigned g_wneg[NOC * NFEAT];
__device__ uint4    g_sv2[NGRP_PAD * NPT];      // [g][pt]; pads never consumed
__device__ int      g_part[NCH * NOC * NPT];    // per-chunk partial diffs

// ---------------------------------------------------------------- max |w|
__global__ void k_maxabs(const float* __restrict__ w, int n) {
    __shared__ float red[32];
    float m = 0.f;
    for (int i = threadIdx.x; i < n; i += blockDim.x)
        m = fmaxf(m, fabsf(w[i]));
    for (int o = 16; o; o >>= 1) m = fmaxf(m, __shfl_xor_sync(0xffffffffu, m, o));
    if ((threadIdx.x & 31) == 0) red[threadIdx.x >> 5] = m;
    __syncthreads();
    if (threadIdx.x < 32) {
        int nw = (blockDim.x + 31) >> 5;
        m = (threadIdx.x < nw) ? red[threadIdx.x] : 0.f;
        for (int o = 16; o; o >>= 1) m = fmaxf(m, __shfl_xor_sync(0xffffffffu, m, o));
        if (threadIdx.x == 0) g_maxabs = (m > 0.f) ? m : 1.f;
    }
}

// ---------------- fused prep: weight bit-slicing + input bit-streaming
#define WB ((NOC * NGRP + 255) / 256)              // 36
#define SB ((NPT * NGRP + 255) / 256)              // 2304
__global__ void k_prep(const float* __restrict__ w, const float* __restrict__ x) {
    if (blockIdx.x < WB) {
        int idx = blockIdx.x * 256 + threadIdx.x;
        if (idx >= NOC * NGRP) return;
        int o = idx / NGRP, g = idx % NGRP;
        float ma = g_maxabs;
        unsigned pw[4] = {0,0,0,0}, nw[4] = {0,0,0,0};
#pragma unroll
        for (int j = 0; j < 4; j++) {
            float r  = w[o * NFEAT + 4 * g + j];
            float wp = fmaxf(r, 0.f);
            float wn = fmaxf(-r, 0.f);
            int pi = (int)rintf(__fdiv_rn(wp, ma) * 255.f);
            int ni = (int)rintf(__fdiv_rn(wn, ma) * 255.f);
#pragma unroll
            for (int t = 0; t < 4; t++) {
                pw[t] |= (unsigned)((pi >> (2 * t)) & 3) << (8 * j);
                nw[t] |= (unsigned)((ni >> (2 * t)) & 3) << (8 * j);
            }
        }
#pragma unroll
        for (int t = 0; t < 4; t++) {
            g_wpos[o * NFEAT + t * NGRP + g] = pw[t];
            g_wneg[o * NFEAT + t * NGRP + g] = nw[t];
        }
    } else {
        int id = (blockIdx.x - WB) * 256 + threadIdx.x;   // NPT*NGRP
        if (id >= NPT * NGRP) return;
        int pt = id & (NPT - 1);
        int g  = id >> 12;
        int b = pt >> 10, p = pt & 1023, h = p >> 5, wc = p & 31;
        unsigned sw0 = 0, sw1 = 0, sw2 = 0, sw3 = 0;
#pragma unroll
        for (int j = 0; j < 4; j++) {
            int f = 4 * g + j;
            int c = f / 9, rem = f - 9 * c, kh = rem / 3, kw = rem - 3 * (rem / 3);
            int y = h + kh - 1, xx = wc + kw - 1;
            float v = 0.f;
            if ((unsigned)y < 32u && (unsigned)xx < 32u)
                v = x[((b * 64 + c) * 32 + y) * 32 + xx];
            v = fminf(fmaxf(v, -8.f), 7.9375f);
            int q = ((int)rintf(v * 16.f)) & 255;
            sw0 |= (unsigned)( q        & 3) << (8 * j);
            sw1 |= (unsigned)((q >> 2)  & 3) << (8 * j);
            sw2 |= (unsigned)((q >> 4)  & 3) << (8 * j);
            sw3 |= (unsigned)((q >> 6)  & 3) << (8 * j);
        }
        g_sv2[g * NPT + pt] = make_uint4(sw0, sw1, sw2, sw3);
    }
}

// ---------------------------------------------------------- main dp4a MAC
// grid (NPT/PTB, NOC/OBLK, NCH). gl-outer / ol-inner (OBLK=2, 64 accs),
// 4-deep LDG prefetch ring for `a` (covers L2 latency via ILP).
// Group loop is compile-time 29; short chunk padded with zero weights.
__global__ __launch_bounds__(PTB, 5) void k_main() {
    __shared__ unsigned s_w[OBLK][29][8];    // [ol][gl][pos t0..3 | neg t0..3]
    const int tid   = threadIdx.x;
    const int pt    = blockIdx.x * PTB + tid;
    const int obase = blockIdx.y * OBLK;
    const int c     = blockIdx.z;
    const int g0    = c * 29;
    const int ng    = (c == 4) ? 28 : 29;

    for (int i = tid; i < OBLK * 29 * 8; i += PTB) {
        int r = i & 7, rest = i >> 3;
        int gl = rest % 29, ol = rest / 29;
        unsigned v = 0;
        if (gl < ng) {
            const unsigned* src = (r < 4) ? g_wpos : g_wneg;
            v = src[(obase + ol) * NFEAT + (r & 3) * NGRP + g0 + gl];
        }
        s_w[ol][gl][r] = v;   // zero rows for gl >= ng
    }
    __syncthreads();

    const uint4* __restrict__ sv = g_sv2 + g0 * NPT + pt;

    int accp[OBLK][16], accn[OBLK][16];
#pragma unroll
    for (int ol = 0; ol < OBLK; ol++)
#pragma unroll
        for (int i = 0; i < 16; i++) { accp[ol][i] = 0; accn[ol][i] = 0; }

    // prefetch ring (g_sv2 padded: reads up to g0+31 < 160 are in-bounds)
    uint4 abuf[4];
    abuf[0] = sv[0 * NPT];
    abuf[1] = sv[1 * NPT];
    abuf[2] = sv[2 * NPT];

#pragma unroll
    for (int gl = 0; gl < 29; gl++) {
        abuf[(gl + 3) & 3] = sv[(gl + 3) * NPT];     // prefetch 3 ahead
        const uint4 a = abuf[gl & 3];
        const unsigned av[4] = {a.x, a.y, a.z, a.w};
#pragma unroll
        for (int ol = 0; ol < OBLK; ol++) {
            uint4 wp = *reinterpret_cast<const uint4*>(&s_w[ol][gl][0]);  // LDS.128
            uint4 wn = *reinterpret_cast<const uint4*>(&s_w[ol][gl][4]);  // LDS.128
            const unsigned pv[4] = {wp.x, wp.y, wp.z, wp.w};
            const unsigned nv[4] = {wn.x, wn.y, wn.z, wn.w};
#pragma unroll
            for (int s = 0; s < 4; s++)
#pragma unroll
                for (int t = 0; t < 4; t++) {
                    accp[ol][s * 4 + t] = __dp4a((int)av[s], (int)pv[t], accp[ol][s * 4 + t]);
                    accn[ol][s * 4 + t] = __dp4a((int)av[s], (int)nv[t], accn[ol][s * 4 + t]);
                }
        }
    }

#pragma unroll
    for (int ol = 0; ol < OBLK; ol++) {
        int diff = 0;
#pragma unroll
        for (int s = 0; s < 4; s++)
#pragma unroll
            for (int t = 0; t < 4; t++)
                diff += (min(accp[ol][s * 4 + t], 31) - min(accn[ol][s * 4 + t], 31))
                        << (2 * (s + t));
        g_part[((c * NOC + obase + ol) << 12) + pt] = diff;
    }
}

// -------------------- combine partials + scale + tail zero (fused)
__global__ void k_final(float* __restrict__ out, int out_size) {
    int id = blockIdx.x * blockDim.x + threadIdx.x;
    if (id < NOC * NPT) {
        int oc = id >> 12, pt = id & (NPT - 1);
        int b = pt >> 10, p = pt & 1023;
        int d = 0;
#pragma unroll
        for (int c = 0; c < NCH; c++)
            d += g_part[((c * NOC + oc) << 12) + pt];
        out[((b * NOC + oc) << 10) + p] = (float)d * (g_maxabs * (1.0f / 255.0f));
    } else if (id < out_size) {
        out[id] = 0.f;   // aux-loss scalar / padding tail
    }
}

extern "C" void kernel_launch(void* const* d_in, const int* in_sizes, int n_in,
                              void* d_out, int out_size) {
    const float* x = (const float*)d_in[0];   // inputs (4,64,32,32)
    const float* w = (const float*)d_in[1];   // weight (64,64,3,3)
    float* out = (float*)d_out;

    k_maxabs<<<1, 1024>>>(w, in_sizes[1]);
    k_prep  <<<WB + SB, 256>>>(w, x);
    k_main  <<<dim3(NPT / PTB, NOC / OBLK, NCH), PTB>>>();
    int fin = (out_size > NOC * NPT) ? out_size : NOC * NPT;
    k_final <<<(fin + 255) / 256, 256>>>(out, out_size);
}